// round 7
// baseline (speedup 1.0000x reference)
#include <cuda_runtime.h>
#include <cuda_fp16.h>
#include <math.h>
#include <stdint.h>

#define NTOK 2048
#define DIMV 1024
#define NEXP 8
#define HDIM 2048

#define MT 64
#define NT 256
#define BK 64              // halves per K chunk = 128 bytes per row

// smem: 2 stages of (A: 64*128B = 8KB) + (B: 256*128B = 32KB)
#define SA_ST 8192
#define SB_BASE 16384
#define SB_ST 32768
#define SMEM_BYTES (SB_BASE + 2 * SB_ST)   // 81920

// ---------------- scratch ----------------
__device__ int   g_counts[NEXP];
__device__ int   g_offsets[NEXP];
__device__ int   g_perm[NEXP * NTOK];
__device__ float g_pw[NEXP * NTOK];
__device__ __align__(16) __half g_xh[NTOK * DIMV];
__device__ __align__(16) __half g_w1h[(size_t)NEXP * HDIM * DIMV];
__device__ __align__(16) __half g_w2h[(size_t)NEXP * DIMV * HDIM];
__device__ __align__(16) __half g_hh[(size_t)2 * NTOK * HDIM];

// ---------------- PTX helpers ----------------
__device__ __forceinline__ uint32_t smem_u32(const void* p) {
    uint32_t a;
    asm("{ .reg .u64 t; cvta.to.shared.u64 t, %1; cvt.u32.u64 %0, t; }" : "=r"(a) : "l"(p));
    return a;
}
#define CPASYNC16(dst, src, sz) \
    asm volatile("cp.async.cg.shared.global [%0], [%1], 16, %2;" :: "r"(dst), "l"(src), "r"(sz) : "memory")
#define CPCOMMIT() asm volatile("cp.async.commit_group;" ::: "memory")

#define LDSM_X4(r0, r1, r2, r3, addr) \
    asm volatile("ldmatrix.sync.aligned.m8n8.x4.shared.b16 {%0,%1,%2,%3}, [%4];" \
        : "=r"(r0), "=r"(r1), "=r"(r2), "=r"(r3) : "r"(addr))

#define MMA16816(d, a, b0, b1) \
    asm volatile("mma.sync.aligned.m16n8k16.row.col.f32.f16.f16.f32 " \
        "{%0,%1,%2,%3},{%4,%5,%6,%7},{%8,%9},{%0,%1,%2,%3};" \
        : "+f"((d)[0]), "+f"((d)[1]), "+f"((d)[2]), "+f"((d)[3]) \
        : "r"((a)[0]), "r"((a)[1]), "r"((a)[2]), "r"((a)[3]), "r"(b0), "r"(b1))

__device__ __forceinline__ float silu(float v) { return v / (1.f + __expf(-v)); }

// ---------------- 0) zero counters ----------------
__global__ void zero_kernel() {
    if (threadIdx.x < NEXP) g_counts[threadIdx.x] = 0;
}

// ---------------- 1) prep: cvt(w1), zero(out), gate ----------------
// roles: [0,4096) w1 cvt (4 float4/thr) | [4096,4608) zero out | [4608,4864) gate
#define NB_CW 4096
#define NB_Z  512
#define NB_G  256

__global__ void __launch_bounds__(256) prep_kernel(const float4* __restrict__ w1,
                                                   const float*  __restrict__ x,
                                                   const float*  __restrict__ gw,
                                                   const float*  __restrict__ bias,
                                                   float4* __restrict__ out4) {
    int b = blockIdx.x;
    int tid = threadIdx.x;

    if (b < NB_CW) {
        __half2* dst = (__half2*)g_w1h;
#pragma unroll
        for (int it = 0; it < 4; it++) {
            int i = b * 1024 + it * 256 + tid;
            float4 v = w1[i];
            dst[2 * i]     = __floats2half2_rn(v.x, v.y);
            dst[2 * i + 1] = __floats2half2_rn(v.z, v.w);
        }
        return;
    }
    if (b < NB_CW + NB_Z) {
        int bb = b - NB_CW;
#pragma unroll
        for (int it = 0; it < 4; it++)
            out4[bb * 1024 + it * 256 + tid] = make_float4(0.f, 0.f, 0.f, 0.f);
        return;
    }

    // ---- gate role: warp per token
    int wid = tid >> 5, lane = tid & 31;
    int t = (b - NB_CW - NB_Z) * 8 + wid;

    const float4* xr = (const float4*)(x + (size_t)t * DIMV);
    float4 xv[8];
#pragma unroll
    for (int i = 0; i < 8; i++) xv[i] = xr[lane + 32 * i];

    __half* xh = g_xh + (size_t)t * DIMV;
#pragma unroll
    for (int i = 0; i < 8; i++) {
        *(__half2*)(xh + (lane + 32 * i) * 4)     = __floats2half2_rn(xv[i].x, xv[i].y);
        *(__half2*)(xh + (lane + 32 * i) * 4 + 2) = __floats2half2_rn(xv[i].z, xv[i].w);
    }

    const float4* g4 = (const float4*)gw;
    float logit[NEXP];
#pragma unroll
    for (int e = 0; e < NEXP; e++) {
        float acc = 0.f;
#pragma unroll
        for (int i = 0; i < 8; i++) {
            float4 g = __ldg(&g4[e * 256 + lane + 32 * i]);
            acc += xv[i].x * g.x + xv[i].y * g.y + xv[i].z * g.z + xv[i].w * g.w;
        }
#pragma unroll
        for (int s = 16; s > 0; s >>= 1) acc += __shfl_xor_sync(0xFFFFFFFFu, acc, s);
        logit[e] = acc;
    }

    if (lane == 0) {
        float sc[NEXP];
#pragma unroll
        for (int e = 0; e < NEXP; e++)
            sc[e] = 1.f / (1.f + __expf(-(logit[e] + bias[e])));
        int i0 = 0;
#pragma unroll
        for (int e = 1; e < NEXP; e++) if (sc[e] > sc[i0]) i0 = e;
        int i1 = (i0 == 0) ? 1 : 0;
#pragma unroll
        for (int e = 0; e < NEXP; e++)
            if (e != i0 && sc[e] > sc[i1]) i1 = e;

        float s0 = sc[i0], s1 = sc[i1];
        float inv = 1.f / (s0 + s1 + 1e-6f);

        int slot0 = atomicAdd(&g_counts[i0], 1);
        g_perm[i0 * NTOK + slot0] = t;
        g_pw[i0 * NTOK + slot0]   = s0 * inv;
        int slot1 = atomicAdd(&g_counts[i1], 1);
        g_perm[i1 * NTOK + slot1] = t;
        g_pw[i1 * NTOK + slot1]   = s1 * inv;
    }
}

// ---------------- 2) offsets ----------------
__global__ void offsets_kernel() {
    if (threadIdx.x == 0) {
        int s = 0;
        for (int e = 0; e < NEXP; e++) { g_offsets[e] = s; s += g_counts[e]; }
    }
}

// ---------------- 3) fp16 mma.sync grouped GEMM, 256 thr, 2 CTAs/SM ----------------
// C[64,256] = A[64,K] @ B[256,K]^T per expert tile.
// 8 warps as 2(m) x 4(n); warp tile 32x64; 2-stage cp.async double buffer.
// gemm1 additionally carries cvt(w2) role-blocks after the gemm blocks.
#define NGEMM_BLK(MTILES, NTILES) (NEXP * (MTILES) * (NTILES))
#define NB_CW2 4096

template <int KTOT, int NTOTAL, bool IS_G1>
__global__ void __launch_bounds__(256, 2) gemm_mma(const __half* __restrict__ Ah,
                                                   const __half* __restrict__ Wh,
                                                   float* __restrict__ out,
                                                   const float4* __restrict__ w2f4) {
    constexpr int MTILES = NTOK * 2 / MT / NEXP * 2;   // 32 m-tiles (covers worst skew? see below)
    constexpr int NTILES = NTOTAL / NT;
    int bid = blockIdx.x;

    if (IS_G1 && bid >= NEXP * 32 * NTILES) {
        // ---- cvt(w2) role
        int cb = bid - NEXP * 32 * NTILES;
        int tid = threadIdx.x;
        __half2* dst = (__half2*)g_w2h;
#pragma unroll
        for (int it = 0; it < 4; it++) {
            int i = cb * 1024 + it * 256 + tid;
            float4 v = w2f4[i];
            dst[2 * i]     = __floats2half2_rn(v.x, v.y);
            dst[2 * i + 1] = __floats2half2_rn(v.z, v.w);
        }
        return;
    }

    // decode: bid = ((e * 32) + m) * NTILES + n
    int n_idx = bid % NTILES;
    int rem   = bid / NTILES;
    int m_idx = rem & 31;
    int e     = rem >> 5;

    int cnt = g_counts[e];
    int m0  = m_idx * MT;
    if (m0 >= cnt) return;
    int n0  = n_idx * NT;
    int off = g_offsets[e];

    extern __shared__ char smem[];
    uint32_t sb = smem_u32(smem);
    int tid = threadIdx.x, wid = tid >> 5, lane = tid & 31;

    // ---- staging: A row = tid>>2 (4 thr/row, 2 x 16B); B row = tid (8 x 16B)
    int ra = tid >> 2, qa = tid & 3;
    bool avalid = (m0 + ra) < cnt;
    const __half* asrc;
    if (IS_G1) {
        int tok = avalid ? g_perm[e * NTOK + m0 + ra] : 0;
        asrc = Ah + (size_t)tok * KTOT + qa * 16;
    } else {
        asrc = Ah + (size_t)(avalid ? (off + m0 + ra) : 0) * KTOT + qa * 16;
    }
    const __half* bsrc = Wh + (size_t)e * NTOTAL * KTOT + (size_t)(n0 + tid) * KTOT;
    uint32_t adst0 = sb + (uint32_t)ra * 128;
    uint32_t bdst0 = sb + SB_BASE + (uint32_t)tid * 128;
    uint32_t asz = avalid ? 16u : 0u;
    uint32_t rxa = (uint32_t)(ra & 7);
    uint32_t rxb = (uint32_t)(tid & 7);

    auto issue = [&](int kc, int st) {
        uint32_t ab = adst0 + st * SA_ST;
        const __half* as = asrc + kc * BK;
#pragma unroll
        for (int j = 0; j < 2; j++) {
            uint32_t ch = (uint32_t)(qa * 2 + j);
            CPASYNC16(ab + ((ch ^ rxa) << 4), as + j * 8, asz);
        }
        uint32_t bb = bdst0 + st * SB_ST;
        const __half* bs = bsrc + kc * BK;
#pragma unroll
        for (int j = 0; j < 8; j++)
            CPASYNC16(bb + (((uint32_t)j ^ rxb) << 4), bs + j * 8, 16u);
        CPCOMMIT();
    };

    // ---- fragment geometry: warp tile 32(m) x 64(n), warps 2m x 4n
    int wm = wid >> 2, wn = wid & 3;
    int m_base = wm * 32, n_base = wn * 64;
    int lr8 = lane & 7, q = lane >> 3;

    int rowA[2], rowB[4];
#pragma unroll
    for (int mi = 0; mi < 2; mi++) rowA[mi] = m_base + mi * 16 + (q & 1) * 8 + lr8;
#pragma unroll
    for (int np = 0; np < 4; np++) rowB[np] = n_base + np * 16 + (q >> 1) * 8 + lr8;

    float acc[2][8][4];
#pragma unroll
    for (int mi = 0; mi < 2; mi++)
#pragma unroll
        for (int nj = 0; nj < 8; nj++)
#pragma unroll
            for (int c = 0; c < 4; c++) acc[mi][nj][c] = 0.f;

    constexpr int NC = KTOT / BK;
    issue(0, 0);
    issue(1, 1);

    for (int kc = 0; kc < NC; kc++) {
        int st = kc & 1;
        if (kc + 1 < NC) {
            asm volatile("cp.async.wait_group 1;" ::: "memory");
        } else {
            asm volatile("cp.async.wait_group 0;" ::: "memory");
        }
        __syncthreads();

        uint32_t Ab = sb + st * SA_ST;
        uint32_t Bb = sb + SB_BASE + st * SB_ST;
#pragma unroll
        for (int s = 0; s < 4; s++) {
            uint32_t a[2][4];
#pragma unroll
            for (int mi = 0; mi < 2; mi++) {
                uint32_t ch = (uint32_t)(s * 2 + (q >> 1));
                uint32_t ad = Ab + (uint32_t)rowA[mi] * 128 + ((ch ^ (uint32_t)(rowA[mi] & 7)) << 4);
                LDSM_X4(a[mi][0], a[mi][1], a[mi][2], a[mi][3], ad);
            }
#pragma unroll
            for (int np = 0; np < 4; np++) {
                uint32_t b0, b1, b2, b3;
                uint32_t ch = (uint32_t)(s * 2 + (q & 1));
                uint32_t bd = Bb + (uint32_t)rowB[np] * 128 + ((ch ^ (uint32_t)(rowB[np] & 7)) << 4);
                LDSM_X4(b0, b1, b2, b3, bd);
#pragma unroll
                for (int mi = 0; mi < 2; mi++) {
                    MMA16816(acc[mi][2 * np],     a[mi], b0, b1);
                    MMA16816(acc[mi][2 * np + 1], a[mi], b2, b3);
                }
            }
        }
        __syncthreads();                    // stage st free for reuse
        if (kc + 2 < NC) issue(kc + 2, st);
    }

    // ---- epilogue
    int g = lane >> 2, t2 = (lane & 3) * 2;
#pragma unroll
    for (int mi = 0; mi < 2; mi++) {
        int r0 = m_base + mi * 16 + g;
        int r1 = r0 + 8;
        bool v0 = (m0 + r0) < cnt;
        bool v1 = (m0 + r1) < cnt;
        if (IS_G1) {
            size_t gr0 = (size_t)(off + m0 + r0);
            size_t gr1 = (size_t)(off + m0 + r1);
#pragma unroll
            for (int nj = 0; nj < 8; nj++) {
                int col = n0 + n_base + nj * 8 + t2;
                if (v0)
                    *(__half2*)(g_hh + gr0 * NTOTAL + col) =
                        __floats2half2_rn(silu(acc[mi][nj][0]), silu(acc[mi][nj][1]));
                if (v1)
                    *(__half2*)(g_hh + gr1 * NTOTAL + col) =
                        __floats2half2_rn(silu(acc[mi][nj][2]), silu(acc[mi][nj][3]));
            }
        } else {
            int tok0 = 0, tok1 = 0;
            float wt0 = 0.f, wt1 = 0.f;
            if (v0) { tok0 = g_perm[e * NTOK + m0 + r0]; wt0 = g_pw[e * NTOK + m0 + r0]; }
            if (v1) { tok1 = g_perm[e * NTOK + m0 + r1]; wt1 = g_pw[e * NTOK + m0 + r1]; }
#pragma unroll
            for (int nj = 0; nj < 8; nj++) {
                int col = n0 + n_base + nj * 8 + t2;
                if (v0) {
                    float* o = out + (size_t)tok0 * DIMV + col;
                    atomicAdd(o,     wt0 * acc[mi][nj][0]);
                    atomicAdd(o + 1, wt0 * acc[mi][nj][1]);
                }
                if (v1) {
                    float* o = out + (size_t)tok1 * DIMV + col;
                    atomicAdd(o,     wt1 * acc[mi][nj][2]);
                    atomicAdd(o + 1, wt1 * acc[mi][nj][3]);
                }
            }
        }
    }
}

// ---------------- launch ----------------
extern "C" void kernel_launch(void* const* d_in, const int* in_sizes, int n_in,
                              void* d_out, int out_size) {
    const float* x      = (const float*)d_in[0];
    const float* gate_w = (const float*)d_in[1];
    const float* bias   = (const float*)d_in[2];
    const float* w1     = (const float*)d_in[3];
    const float* w2     = (const float*)d_in[4];
    float* out          = (float*)d_out;

    cudaFuncSetAttribute(gemm_mma<DIMV, HDIM, true>,
                         cudaFuncAttributeMaxDynamicSharedMemorySize, SMEM_BYTES);
    cudaFuncSetAttribute(gemm_mma<HDIM, DIMV, false>,
                         cudaFuncAttributeMaxDynamicSharedMemorySize, SMEM_BYTES);

    zero_kernel<<<1, 32>>>();
    prep_kernel<<<NB_CW + NB_Z + NB_G, 256>>>((const float4*)w1, x, gate_w, bias, (float4*)out);
    offsets_kernel<<<1, 32>>>();

    __half* xh;  cudaGetSymbolAddress((void**)&xh, g_xh);
    __half* hh;  cudaGetSymbolAddress((void**)&hh, g_hh);
    __half* w1h; cudaGetSymbolAddress((void**)&w1h, g_w1h);
    __half* w2h; cudaGetSymbolAddress((void**)&w2h, g_w2h);

    // gemm1: 8 experts * 32 m-tiles * 8 n-tiles = 2048 blocks, + 4096 cvt(w2) blocks
    gemm_mma<DIMV, HDIM, true><<<NEXP * 32 * (HDIM / NT) + NB_CW2, 256, SMEM_BYTES>>>(
        xh, w1h, nullptr, (const float4*)w2);
    // gemm2: 8 * 32 * 4 = 1024 blocks
    gemm_mma<HDIM, DIMV, false><<<NEXP * 32 * (DIMV / NT), 256, SMEM_BYTES>>>(
        hh, w2h, out, nullptr);
}

// round 8
// speedup vs baseline: 1.1760x; 1.1760x over previous
#include <cuda_runtime.h>
#include <cuda_fp16.h>
#include <math.h>
#include <stdint.h>

#define NTOK 2048
#define DIMV 1024
#define NEXP 8
#define HDIM 2048

#define MT 128
#define NT 128
#define BK 64              // halves per K chunk = 128 bytes per row

// smem: 3 stages of (A: 128*128B = 16KB) + (B: 128*128B = 16KB)
#define SA_ST 16384
#define SB_BASE 49152
#define SB_ST 16384
#define SMEM_BYTES (SB_BASE + 3 * SB_ST)   // 98304

// ---------------- scratch ----------------
__device__ int   g_counts[NEXP];
__device__ int   g_offsets[NEXP];
__device__ int   g_perm[NEXP * NTOK];
__device__ float g_pw[NEXP * NTOK];
__device__ __align__(16) __half g_xh[NTOK * DIMV];
__device__ __align__(16) __half g_w1h[(size_t)NEXP * HDIM * DIMV];
__device__ __align__(16) __half g_w2h[(size_t)NEXP * DIMV * HDIM];
__device__ __align__(16) __half g_hh[(size_t)2 * NTOK * HDIM];

// ---------------- PTX helpers ----------------
__device__ __forceinline__ uint32_t smem_u32(const void* p) {
    uint32_t a;
    asm("{ .reg .u64 t; cvta.to.shared.u64 t, %1; cvt.u32.u64 %0, t; }" : "=r"(a) : "l"(p));
    return a;
}
#define CPASYNC16(dst, src, sz) \
    asm volatile("cp.async.cg.shared.global [%0], [%1], 16, %2;" :: "r"(dst), "l"(src), "r"(sz) : "memory")
#define CPCOMMIT() asm volatile("cp.async.commit_group;" ::: "memory")

#define LDSM_X4(r0, r1, r2, r3, addr) \
    asm volatile("ldmatrix.sync.aligned.m8n8.x4.shared.b16 {%0,%1,%2,%3}, [%4];" \
        : "=r"(r0), "=r"(r1), "=r"(r2), "=r"(r3) : "r"(addr))

#define MMA16816(d, a, b0, b1) \
    asm volatile("mma.sync.aligned.m16n8k16.row.col.f32.f16.f16.f32 " \
        "{%0,%1,%2,%3},{%4,%5,%6,%7},{%8,%9},{%0,%1,%2,%3};" \
        : "+f"((d)[0]), "+f"((d)[1]), "+f"((d)[2]), "+f"((d)[3]) \
        : "r"((a)[0]), "r"((a)[1]), "r"((a)[2]), "r"((a)[3]), "r"(b0), "r"(b1))

__device__ __forceinline__ float silu(float v) { return v / (1.f + __expf(-v)); }

// ---------------- 0) zero counters ----------------
__global__ void zero_kernel() {
    if (threadIdx.x < NEXP) g_counts[threadIdx.x] = 0;
}

// ---------------- 1) fused prep: cvt(w1), cvt(w2), zero(out), gate ----------------
#define NB_W (NEXP * HDIM * DIMV / 4 / 256)    // 16384 blocks per weight tensor
#define NB_Z (NTOK * DIMV / 4 / 256)           // 2048
#define NB_G (NTOK / 8)                        // 256

__global__ void __launch_bounds__(256) prep_kernel(const float4* __restrict__ w1,
                                                   const float4* __restrict__ w2,
                                                   const float*  __restrict__ x,
                                                   const float*  __restrict__ gw,
                                                   const float*  __restrict__ bias,
                                                   float4* __restrict__ out4) {
    int b = blockIdx.x;
    int tid = threadIdx.x;

    if (b < 2 * NB_W) {
        const float4* src = (b < NB_W) ? w1 : w2;
        __half2* dst = (__half2*)((b < NB_W) ? g_w1h : g_w2h);
        int i = (b % NB_W) * 256 + tid;
        float4 v = src[i];
        dst[2 * i]     = __floats2half2_rn(v.x, v.y);
        dst[2 * i + 1] = __floats2half2_rn(v.z, v.w);
        return;
    }
    if (b < 2 * NB_W + NB_Z) {
        int i = (b - 2 * NB_W) * 256 + tid;
        out4[i] = make_float4(0.f, 0.f, 0.f, 0.f);
        return;
    }

    // ---- gate role: warp per token
    int wid = tid >> 5, lane = tid & 31;
    int t = (b - 2 * NB_W - NB_Z) * 8 + wid;

    const float4* xr = (const float4*)(x + (size_t)t * DIMV);
    float4 xv[8];
#pragma unroll
    for (int i = 0; i < 8; i++) xv[i] = xr[lane + 32 * i];

    __half* xh = g_xh + (size_t)t * DIMV;
#pragma unroll
    for (int i = 0; i < 8; i++) {
        *(__half2*)(xh + (lane + 32 * i) * 4)     = __floats2half2_rn(xv[i].x, xv[i].y);
        *(__half2*)(xh + (lane + 32 * i) * 4 + 2) = __floats2half2_rn(xv[i].z, xv[i].w);
    }

    const float4* g4 = (const float4*)gw;
    float logit[NEXP];
#pragma unroll
    for (int e = 0; e < NEXP; e++) {
        float acc = 0.f;
#pragma unroll
        for (int i = 0; i < 8; i++) {
            float4 g = __ldg(&g4[e * 256 + lane + 32 * i]);
            acc += xv[i].x * g.x + xv[i].y * g.y + xv[i].z * g.z + xv[i].w * g.w;
        }
#pragma unroll
        for (int s = 16; s > 0; s >>= 1) acc += __shfl_xor_sync(0xFFFFFFFFu, acc, s);
        logit[e] = acc;
    }

    if (lane == 0) {
        float sc[NEXP];
#pragma unroll
        for (int e = 0; e < NEXP; e++)
            sc[e] = 1.f / (1.f + __expf(-(logit[e] + bias[e])));
        int i0 = 0;
#pragma unroll
        for (int e = 1; e < NEXP; e++) if (sc[e] > sc[i0]) i0 = e;
        int i1 = (i0 == 0) ? 1 : 0;
#pragma unroll
        for (int e = 0; e < NEXP; e++)
            if (e != i0 && sc[e] > sc[i1]) i1 = e;

        float s0 = sc[i0], s1 = sc[i1];
        float inv = 1.f / (s0 + s1 + 1e-6f);

        int slot0 = atomicAdd(&g_counts[i0], 1);
        g_perm[i0 * NTOK + slot0] = t;
        g_pw[i0 * NTOK + slot0]   = s0 * inv;
        int slot1 = atomicAdd(&g_counts[i1], 1);
        g_perm[i1 * NTOK + slot1] = t;
        g_pw[i1 * NTOK + slot1]   = s1 * inv;
    }
}

// ---------------- 2) offsets ----------------
__global__ void offsets_kernel() {
    if (threadIdx.x == 0) {
        int s = 0;
        for (int e = 0; e < NEXP; e++) { g_offsets[e] = s; s += g_counts[e]; }
    }
}

// ---------------- 3) fp16 mma.sync grouped GEMM: 128x128 tile, 2 CTAs/SM ----------------
// C[128,128] = A[128,K] @ B[128,K]^T per expert tile.
// 8 warps as 4(m) x 2(n); warp tile 32x64; 3-stage cp.async pipeline.
template <int KTOT, int NTOTAL, bool IS_G1>
__global__ void __launch_bounds__(256, 2) gemm_mma(const __half* __restrict__ Ah,
                                                   const __half* __restrict__ Wh,
                                                   float* __restrict__ out) {
    int e = blockIdx.z;
    int cnt = g_counts[e];
    int m0 = blockIdx.y * MT;
    if (m0 >= cnt) return;
    int n0 = blockIdx.x * NT;
    int off = g_offsets[e];

    extern __shared__ char smem[];
    uint32_t sb = smem_u32(smem);
    int tid = threadIdx.x, wid = tid >> 5, lane = tid & 31;

    // ---- staging: A and B rows = tid>>1 (2 thr/row, 4 x 16B each)
    int ra = tid >> 1, qa = tid & 1;
    bool avalid = (m0 + ra) < cnt;
    const __half* asrc;
    if (IS_G1) {
        int tok = avalid ? g_perm[e * NTOK + m0 + ra] : 0;
        asrc = Ah + (size_t)tok * KTOT + qa * 32;
    } else {
        asrc = Ah + (size_t)(avalid ? (off + m0 + ra) : 0) * KTOT + qa * 32;
    }
    const __half* bsrc = Wh + (size_t)e * NTOTAL * KTOT + (size_t)(n0 + ra) * KTOT + qa * 32;
    uint32_t adst0 = sb + (uint32_t)ra * 128;
    uint32_t bdst0 = sb + SB_BASE + (uint32_t)ra * 128;
    uint32_t asz = avalid ? 16u : 0u;
    uint32_t rx = (uint32_t)(ra & 7);

    auto issue = [&](int kc, int st) {
        uint32_t ab = adst0 + st * SA_ST;
        const __half* as = asrc + kc * BK;
        uint32_t bb = bdst0 + st * SB_ST;
        const __half* bs = bsrc + kc * BK;
#pragma unroll
        for (int j = 0; j < 4; j++) {
            uint32_t ch = (uint32_t)(qa * 4 + j);
            CPASYNC16(ab + ((ch ^ rx) << 4), as + j * 8, asz);
            CPASYNC16(bb + ((ch ^ rx) << 4), bs + j * 8, 16u);
        }
        CPCOMMIT();
    };

    // ---- fragment geometry: warp tile 32(m) x 64(n), warps 4m x 2n
    int wm = wid >> 1, wn = wid & 1;
    int m_base = wm * 32, n_base = wn * 64;
    int lr8 = lane & 7, q = lane >> 3;

    int rowA[2], rowB[4];
#pragma unroll
    for (int mi = 0; mi < 2; mi++) rowA[mi] = m_base + mi * 16 + (q & 1) * 8 + lr8;
#pragma unroll
    for (int np = 0; np < 4; np++) rowB[np] = n_base + np * 16 + (q >> 1) * 8 + lr8;

    float acc[2][8][4];
#pragma unroll
    for (int mi = 0; mi < 2; mi++)
#pragma unroll
        for (int nj = 0; nj < 8; nj++)
#pragma unroll
            for (int c = 0; c < 4; c++) acc[mi][nj][c] = 0.f;

    constexpr int NC = KTOT / BK;
    issue(0, 0);
    issue(1, 1);

    for (int kc = 0; kc < NC; kc++) {
        int st = kc % 3;
        if (kc + 1 < NC) {
            asm volatile("cp.async.wait_group 1;" ::: "memory");
        } else {
            asm volatile("cp.async.wait_group 0;" ::: "memory");
        }
        __syncthreads();
        if (kc + 2 < NC) issue(kc + 2, (kc + 2) % 3);

        uint32_t Ab = sb + st * SA_ST;
        uint32_t Bb = sb + SB_BASE + st * SB_ST;
#pragma unroll
        for (int s = 0; s < 4; s++) {
            uint32_t a[2][4];
#pragma unroll
            for (int mi = 0; mi < 2; mi++) {
                uint32_t ch = (uint32_t)(s * 2 + (q >> 1));
                uint32_t ad = Ab + (uint32_t)rowA[mi] * 128 + ((ch ^ (uint32_t)(rowA[mi] & 7)) << 4);
                LDSM_X4(a[mi][0], a[mi][1], a[mi][2], a[mi][3], ad);
            }
#pragma unroll
            for (int np = 0; np < 4; np++) {
                uint32_t b0, b1, b2, b3;
                uint32_t ch = (uint32_t)(s * 2 + (q & 1));
                uint32_t bd = Bb + (uint32_t)rowB[np] * 128 + ((ch ^ (uint32_t)(rowB[np] & 7)) << 4);
                LDSM_X4(b0, b1, b2, b3, bd);
#pragma unroll
                for (int mi = 0; mi < 2; mi++) {
                    MMA16816(acc[mi][2 * np],     a[mi], b0, b1);
                    MMA16816(acc[mi][2 * np + 1], a[mi], b2, b3);
                }
            }
        }
    }

    // ---- epilogue
    int g = lane >> 2, t2 = (lane & 3) * 2;
#pragma unroll
    for (int mi = 0; mi < 2; mi++) {
        int r0 = m_base + mi * 16 + g;
        int r1 = r0 + 8;
        bool v0 = (m0 + r0) < cnt;
        bool v1 = (m0 + r1) < cnt;
        if (IS_G1) {
            size_t gr0 = (size_t)(off + m0 + r0);
            size_t gr1 = (size_t)(off + m0 + r1);
#pragma unroll
            for (int nj = 0; nj < 8; nj++) {
                int col = n0 + n_base + nj * 8 + t2;
                if (v0)
                    *(__half2*)(g_hh + gr0 * NTOTAL + col) =
                        __floats2half2_rn(silu(acc[mi][nj][0]), silu(acc[mi][nj][1]));
                if (v1)
                    *(__half2*)(g_hh + gr1 * NTOTAL + col) =
                        __floats2half2_rn(silu(acc[mi][nj][2]), silu(acc[mi][nj][3]));
            }
        } else {
            int tok0 = 0, tok1 = 0;
            float wt0 = 0.f, wt1 = 0.f;
            if (v0) { tok0 = g_perm[e * NTOK + m0 + r0]; wt0 = g_pw[e * NTOK + m0 + r0]; }
            if (v1) { tok1 = g_perm[e * NTOK + m0 + r1]; wt1 = g_pw[e * NTOK + m0 + r1]; }
#pragma unroll
            for (int nj = 0; nj < 8; nj++) {
                int col = n0 + n_base + nj * 8 + t2;
                if (v0) {
                    float* o = out + (size_t)tok0 * DIMV + col;
                    atomicAdd(o,     wt0 * acc[mi][nj][0]);
                    atomicAdd(o + 1, wt0 * acc[mi][nj][1]);
                }
                if (v1) {
                    float* o = out + (size_t)tok1 * DIMV + col;
                    atomicAdd(o,     wt1 * acc[mi][nj][2]);
                    atomicAdd(o + 1, wt1 * acc[mi][nj][3]);
                }
            }
        }
    }
}

// ---------------- launch ----------------
extern "C" void kernel_launch(void* const* d_in, const int* in_sizes, int n_in,
                              void* d_out, int out_size) {
    const float* x      = (const float*)d_in[0];
    const float* gate_w = (const float*)d_in[1];
    const float* bias   = (const float*)d_in[2];
    const float* w1     = (const float*)d_in[3];
    const float* w2     = (const float*)d_in[4];
    float* out          = (float*)d_out;

    cudaFuncSetAttribute(gemm_mma<DIMV, HDIM, true>,
                         cudaFuncAttributeMaxDynamicSharedMemorySize, SMEM_BYTES);
    cudaFuncSetAttribute(gemm_mma<HDIM, DIMV, false>,
                         cudaFuncAttributeMaxDynamicSharedMemorySize, SMEM_BYTES);

    zero_kernel<<<1, 32>>>();
    prep_kernel<<<2 * NB_W + NB_Z + NB_G, 256>>>((const float4*)w1, (const float4*)w2,
                                                 x, gate_w, bias, (float4*)out);
    offsets_kernel<<<1, 32>>>();

    __half* xh;  cudaGetSymbolAddress((void**)&xh, g_xh);
    __half* hh;  cudaGetSymbolAddress((void**)&hh, g_hh);
    __half* w1h; cudaGetSymbolAddress((void**)&w1h, g_w1h);
    __half* w2h; cudaGetSymbolAddress((void**)&w2h, g_w2h);

    // m-tiles: worst-case one expert holds all 2048 tokens -> 16 tiles of 128
    gemm_mma<DIMV, HDIM, true><<<dim3(HDIM / NT, 16, NEXP), 256, SMEM_BYTES>>>(xh, w1h, nullptr);
    gemm_mma<HDIM, DIMV, false><<<dim3(DIMV / NT, 16, NEXP), 256, SMEM_BYTES>>>(hh, w2h, out);
}

// round 9
// speedup vs baseline: 1.1884x; 1.0106x over previous
#include <cuda_runtime.h>
#include <cuda_fp16.h>
#include <math.h>
#include <stdint.h>

#define NTOK 2048
#define DIMV 1024
#define NEXP 8
#define HDIM 2048

#define MT 128
#define NT 256
#define BK 64              // halves per K chunk = 128 bytes per row

// smem: 3 stages of (A: 128*128B = 16KB) + (B: 256*128B = 32KB)
#define SA_ST 16384
#define SB_BASE 49152
#define SB_ST 32768
#define SMEM_BYTES (SB_BASE + 3 * SB_ST)   // 147456

// ---------------- scratch ----------------
__device__ int   g_counts[NEXP];
__device__ int   g_offsets[NEXP];
__device__ int   g_perm[NEXP * NTOK];
__device__ float g_pw[NEXP * NTOK];
__device__ __align__(16) __half g_xh[NTOK * DIMV];
__device__ __align__(16) __half g_w1h[(size_t)NEXP * HDIM * DIMV];
__device__ __align__(16) __half g_w2h[(size_t)NEXP * DIMV * HDIM];
__device__ __align__(16) __half g_hh[(size_t)2 * NTOK * HDIM];

// ---------------- PTX helpers ----------------
__device__ __forceinline__ uint32_t smem_u32(const void* p) {
    uint32_t a;
    asm("{ .reg .u64 t; cvta.to.shared.u64 t, %1; cvt.u32.u64 %0, t; }" : "=r"(a) : "l"(p));
    return a;
}
#define CPASYNC16(dst, src, sz) \
    asm volatile("cp.async.cg.shared.global [%0], [%1], 16, %2;" :: "r"(dst), "l"(src), "r"(sz) : "memory")
#define CPCOMMIT() asm volatile("cp.async.commit_group;" ::: "memory")

#define LDSM_X4(r0, r1, r2, r3, addr) \
    asm volatile("ldmatrix.sync.aligned.m8n8.x4.shared.b16 {%0,%1,%2,%3}, [%4];" \
        : "=r"(r0), "=r"(r1), "=r"(r2), "=r"(r3) : "r"(addr))

#define MMA16816(d, a, b0, b1) \
    asm volatile("mma.sync.aligned.m16n8k16.row.col.f32.f16.f16.f32 " \
        "{%0,%1,%2,%3},{%4,%5,%6,%7},{%8,%9},{%0,%1,%2,%3};" \
        : "+f"((d)[0]), "+f"((d)[1]), "+f"((d)[2]), "+f"((d)[3]) \
        : "r"((a)[0]), "r"((a)[1]), "r"((a)[2]), "r"((a)[3]), "r"(b0), "r"(b1))

__device__ __forceinline__ float silu(float v) { return v / (1.f + __expf(-v)); }

// ---------------- 0) zero counters ----------------
__global__ void zero_kernel() {
    if (threadIdx.x < NEXP) g_counts[threadIdx.x] = 0;
}

// ---------------- 1) fused prep: cvt(w1), cvt(w2), zero(out), gate ----------------
#define NB_W (NEXP * HDIM * DIMV / 4 / 256)    // 16384 blocks per weight tensor
#define NB_Z (NTOK * DIMV / 4 / 256)           // 2048
#define NB_G (NTOK / 8)                        // 256

__global__ void __launch_bounds__(256) prep_kernel(const float4* __restrict__ w1,
                                                   const float4* __restrict__ w2,
                                                   const float*  __restrict__ x,
                                                   const float*  __restrict__ gw,
                                                   const float*  __restrict__ bias,
                                                   float4* __restrict__ out4) {
    int b = blockIdx.x;
    int tid = threadIdx.x;

    if (b < 2 * NB_W) {
        const float4* src = (b < NB_W) ? w1 : w2;
        __half2* dst = (__half2*)((b < NB_W) ? g_w1h : g_w2h);
        int i = (b % NB_W) * 256 + tid;
        float4 v = src[i];
        dst[2 * i]     = __floats2half2_rn(v.x, v.y);
        dst[2 * i + 1] = __floats2half2_rn(v.z, v.w);
        return;
    }
    if (b < 2 * NB_W + NB_Z) {
        int i = (b - 2 * NB_W) * 256 + tid;
        out4[i] = make_float4(0.f, 0.f, 0.f, 0.f);
        return;
    }

    // ---- gate role: warp per token
    int wid = tid >> 5, lane = tid & 31;
    int t = (b - 2 * NB_W - NB_Z) * 8 + wid;

    const float4* xr = (const float4*)(x + (size_t)t * DIMV);
    float4 xv[8];
#pragma unroll
    for (int i = 0; i < 8; i++) xv[i] = xr[lane + 32 * i];

    __half* xh = g_xh + (size_t)t * DIMV;
#pragma unroll
    for (int i = 0; i < 8; i++) {
        *(__half2*)(xh + (lane + 32 * i) * 4)     = __floats2half2_rn(xv[i].x, xv[i].y);
        *(__half2*)(xh + (lane + 32 * i) * 4 + 2) = __floats2half2_rn(xv[i].z, xv[i].w);
    }

    const float4* g4 = (const float4*)gw;
    float logit[NEXP];
#pragma unroll
    for (int e = 0; e < NEXP; e++) {
        float acc = 0.f;
#pragma unroll
        for (int i = 0; i < 8; i++) {
            float4 g = __ldg(&g4[e * 256 + lane + 32 * i]);
            acc += xv[i].x * g.x + xv[i].y * g.y + xv[i].z * g.z + xv[i].w * g.w;
        }
#pragma unroll
        for (int s = 16; s > 0; s >>= 1) acc += __shfl_xor_sync(0xFFFFFFFFu, acc, s);
        logit[e] = acc;
    }

    if (lane == 0) {
        float sc[NEXP];
#pragma unroll
        for (int e = 0; e < NEXP; e++)
            sc[e] = 1.f / (1.f + __expf(-(logit[e] + bias[e])));
        int i0 = 0;
#pragma unroll
        for (int e = 1; e < NEXP; e++) if (sc[e] > sc[i0]) i0 = e;
        int i1 = (i0 == 0) ? 1 : 0;
#pragma unroll
        for (int e = 0; e < NEXP; e++)
            if (e != i0 && sc[e] > sc[i1]) i1 = e;

        float s0 = sc[i0], s1 = sc[i1];
        float inv = 1.f / (s0 + s1 + 1e-6f);

        int slot0 = atomicAdd(&g_counts[i0], 1);
        g_perm[i0 * NTOK + slot0] = t;
        g_pw[i0 * NTOK + slot0]   = s0 * inv;
        int slot1 = atomicAdd(&g_counts[i1], 1);
        g_perm[i1 * NTOK + slot1] = t;
        g_pw[i1 * NTOK + slot1]   = s1 * inv;
    }
}

// ---------------- 2) offsets ----------------
__global__ void offsets_kernel() {
    if (threadIdx.x == 0) {
        int s = 0;
        for (int e = 0; e < NEXP; e++) { g_offsets[e] = s; s += g_counts[e]; }
    }
}

// ---------------- 3) fp16 mma.sync grouped GEMM, 512 threads, optional K-split ----------------
// C[128,256] = A[128,Kslice] @ B[256,Kslice]^T per expert tile.
// 16 warps as 4(m) x 4(n); warp tile 32x64; 3-stage cp.async, one sync/chunk.
template <int KTOT, int NTOTAL, bool IS_G1, int KSP>
__global__ void __launch_bounds__(512, 1) gemm_mma(const __half* __restrict__ Ah,
                                                   const __half* __restrict__ Wh,
                                                   float* __restrict__ out) {
    int ks = (KSP > 1) ? ((int)blockIdx.z % KSP) : 0;
    int e  = (int)blockIdx.z / KSP;
    int cnt = g_counts[e];
    int m0 = blockIdx.y * MT;
    if (m0 >= cnt) return;
    int n0 = blockIdx.x * NT;
    int off = g_offsets[e];
    int kbase = ks * (KTOT / KSP);

    extern __shared__ char smem[];
    uint32_t sb = smem_u32(smem);
    int tid = threadIdx.x, wid = tid >> 5, lane = tid & 31;

    // ---- staging: A row = tid>>2 (4 thr/row, 2 x 16B each); B row = tid>>1 (2 thr/row, 4 x 16B)
    int ra = tid >> 2, qa = tid & 3;
    int rb = tid >> 1, qb = tid & 1;
    bool avalid = (m0 + ra) < cnt;
    const __half* asrc;
    if (IS_G1) {
        int tok = avalid ? g_perm[e * NTOK + m0 + ra] : 0;
        asrc = Ah + (size_t)tok * KTOT + kbase + qa * 16;
    } else {
        asrc = Ah + (size_t)(avalid ? (off + m0 + ra) : 0) * KTOT + kbase + qa * 16;
    }
    const __half* bsrc = Wh + (size_t)e * NTOTAL * KTOT + (size_t)(n0 + rb) * KTOT + kbase + qb * 32;
    uint32_t adst0 = sb + (uint32_t)ra * 128;
    uint32_t bdst0 = sb + SB_BASE + (uint32_t)rb * 128;
    uint32_t asz = avalid ? 16u : 0u;
    uint32_t rxa = (uint32_t)(ra & 7);
    uint32_t rxb = (uint32_t)(rb & 7);

    auto issue = [&](int kc, int st) {
        uint32_t ab = adst0 + st * SA_ST;
        const __half* as = asrc + kc * BK;
#pragma unroll
        for (int j = 0; j < 2; j++) {
            uint32_t ch = (uint32_t)(qa * 2 + j);
            CPASYNC16(ab + ((ch ^ rxa) << 4), as + j * 8, asz);
        }
        uint32_t bb = bdst0 + st * SB_ST;
        const __half* bs = bsrc + kc * BK;
#pragma unroll
        for (int j = 0; j < 4; j++) {
            uint32_t ch = (uint32_t)(qb * 4 + j);
            CPASYNC16(bb + ((ch ^ rxb) << 4), bs + j * 8, 16u);
        }
        CPCOMMIT();
    };

    // ---- fragment geometry: warp tile 32(m) x 64(n), warps 4m x 4n
    int wm = wid >> 2, wn = wid & 3;
    int m_base = wm * 32, n_base = wn * 64;
    int lr8 = lane & 7, q = lane >> 3;

    int rowA[2], rowB[4];
#pragma unroll
    for (int mi = 0; mi < 2; mi++) rowA[mi] = m_base + mi * 16 + (q & 1) * 8 + lr8;
#pragma unroll
    for (int np = 0; np < 4; np++) rowB[np] = n_base + np * 16 + (q >> 1) * 8 + lr8;

    float acc[2][8][4];
#pragma unroll
    for (int mi = 0; mi < 2; mi++)
#pragma unroll
        for (int nj = 0; nj < 8; nj++)
#pragma unroll
            for (int c = 0; c < 4; c++) acc[mi][nj][c] = 0.f;

    constexpr int NC = KTOT / BK / KSP;
    issue(0, 0);
    issue(1, 1);

    for (int kc = 0; kc < NC; kc++) {
        int st = kc % 3;
        if (kc + 1 < NC) {
            asm volatile("cp.async.wait_group 1;" ::: "memory");
        } else {
            asm volatile("cp.async.wait_group 0;" ::: "memory");
        }
        __syncthreads();
        if (kc + 2 < NC) issue(kc + 2, (kc + 2) % 3);

        uint32_t Ab = sb + st * SA_ST;
        uint32_t Bb = sb + SB_BASE + st * SB_ST;
#pragma unroll
        for (int s = 0; s < 4; s++) {
            uint32_t a[2][4];
#pragma unroll
            for (int mi = 0; mi < 2; mi++) {
                uint32_t ch = (uint32_t)(s * 2 + (q >> 1));
                uint32_t ad = Ab + (uint32_t)rowA[mi] * 128 + ((ch ^ (uint32_t)(rowA[mi] & 7)) << 4);
                LDSM_X4(a[mi][0], a[mi][1], a[mi][2], a[mi][3], ad);
            }
#pragma unroll
            for (int np = 0; np < 4; np++) {
                uint32_t b0, b1, b2, b3;
                uint32_t ch = (uint32_t)(s * 2 + (q & 1));
                uint32_t bd = Bb + (uint32_t)rowB[np] * 128 + ((ch ^ (uint32_t)(rowB[np] & 7)) << 4);
                LDSM_X4(b0, b1, b2, b3, bd);
#pragma unroll
                for (int mi = 0; mi < 2; mi++) {
                    MMA16816(acc[mi][2 * np],     a[mi], b0, b1);
                    MMA16816(acc[mi][2 * np + 1], a[mi], b2, b3);
                }
            }
        }
    }

    // ---- epilogue
    int g = lane >> 2, t2 = (lane & 3) * 2;
#pragma unroll
    for (int mi = 0; mi < 2; mi++) {
        int r0 = m_base + mi * 16 + g;
        int r1 = r0 + 8;
        bool v0 = (m0 + r0) < cnt;
        bool v1 = (m0 + r1) < cnt;
        if (IS_G1) {
            size_t gr0 = (size_t)(off + m0 + r0);
            size_t gr1 = (size_t)(off + m0 + r1);
#pragma unroll
            for (int nj = 0; nj < 8; nj++) {
                int col = n0 + n_base + nj * 8 + t2;
                if (v0)
                    *(__half2*)(g_hh + gr0 * NTOTAL + col) =
                        __floats2half2_rn(silu(acc[mi][nj][0]), silu(acc[mi][nj][1]));
                if (v1)
                    *(__half2*)(g_hh + gr1 * NTOTAL + col) =
                        __floats2half2_rn(silu(acc[mi][nj][2]), silu(acc[mi][nj][3]));
            }
        } else {
            int tok0 = 0, tok1 = 0;
            float wt0 = 0.f, wt1 = 0.f;
            if (v0) { tok0 = g_perm[e * NTOK + m0 + r0]; wt0 = g_pw[e * NTOK + m0 + r0]; }
            if (v1) { tok1 = g_perm[e * NTOK + m0 + r1]; wt1 = g_pw[e * NTOK + m0 + r1]; }
#pragma unroll
            for (int nj = 0; nj < 8; nj++) {
                int col = n0 + n_base + nj * 8 + t2;
                if (v0) {
                    float* o = out + (size_t)tok0 * DIMV + col;
                    atomicAdd(o,     wt0 * acc[mi][nj][0]);
                    atomicAdd(o + 1, wt0 * acc[mi][nj][1]);
                }
                if (v1) {
                    float* o = out + (size_t)tok1 * DIMV + col;
                    atomicAdd(o,     wt1 * acc[mi][nj][2]);
                    atomicAdd(o + 1, wt1 * acc[mi][nj][3]);
                }
            }
        }
    }
}

// ---------------- launch ----------------
extern "C" void kernel_launch(void* const* d_in, const int* in_sizes, int n_in,
                              void* d_out, int out_size) {
    const float* x      = (const float*)d_in[0];
    const float* gate_w = (const float*)d_in[1];
    const float* bias   = (const float*)d_in[2];
    const float* w1     = (const float*)d_in[3];
    const float* w2     = (const float*)d_in[4];
    float* out          = (float*)d_out;

    cudaFuncSetAttribute(gemm_mma<DIMV, HDIM, true, 1>,
                         cudaFuncAttributeMaxDynamicSharedMemorySize, SMEM_BYTES);
    cudaFuncSetAttribute(gemm_mma<HDIM, DIMV, false, 2>,
                         cudaFuncAttributeMaxDynamicSharedMemorySize, SMEM_BYTES);

    zero_kernel<<<1, 32>>>();
    prep_kernel<<<2 * NB_W + NB_Z + NB_G, 256>>>((const float4*)w1, (const float4*)w2,
                                                 x, gate_w, bias, (float4*)out);
    offsets_kernel<<<1, 32>>>();

    __half* xh;  cudaGetSymbolAddress((void**)&xh, g_xh);
    __half* hh;  cudaGetSymbolAddress((void**)&hh, g_hh);
    __half* w1h; cudaGetSymbolAddress((void**)&w1h, g_w1h);
    __half* w2h; cudaGetSymbolAddress((void**)&w2h, g_w2h);

    gemm_mma<DIMV, HDIM, true, 1><<<dim3(HDIM / NT, NTOK / MT, NEXP), 512, SMEM_BYTES>>>(xh, w1h, nullptr);
    gemm_mma<HDIM, DIMV, false, 2><<<dim3(DIMV / NT, NTOK / MT, NEXP * 2), 512, SMEM_BYTES>>>(hh, w2h, out);
}

// round 10
// speedup vs baseline: 1.2879x; 1.0837x over previous
#include <cuda_runtime.h>
#include <cuda_fp16.h>
#include <math.h>
#include <stdint.h>

#define NTOK 2048
#define DIMV 1024
#define NEXP 8
#define HDIM 2048

#define MT 128
#define NT 256
#define BK 64              // halves per K chunk = 128 bytes per row

// smem: 3 stages of (A: 128*128B = 16KB) + (B: 256*128B = 32KB)
#define SA_ST 16384
#define SB_BASE 49152
#define SB_ST 32768
#define SMEM_BYTES (SB_BASE + 3 * SB_ST)   // 147456

// ---------------- scratch ----------------
__device__ int   g_counts[NEXP];
__device__ int   g_offsets[NEXP];
__device__ int   g_perm[NEXP * NTOK];
__device__ float g_pw[NEXP * NTOK];
__device__ __align__(16) __half g_xh[NTOK * DIMV];
__device__ __align__(16) __half g_w1h[(size_t)NEXP * HDIM * DIMV];
__device__ __align__(16) __half g_w2h[(size_t)NEXP * DIMV * HDIM];
__device__ __align__(16) __half g_hh[(size_t)2 * NTOK * HDIM];

// ---------------- PTX helpers ----------------
__device__ __forceinline__ uint32_t smem_u32(const void* p) {
    uint32_t a;
    asm("{ .reg .u64 t; cvta.to.shared.u64 t, %1; cvt.u32.u64 %0, t; }" : "=r"(a) : "l"(p));
    return a;
}
#define CPASYNC16(dst, src, sz) \
    asm volatile("cp.async.cg.shared.global [%0], [%1], 16, %2;" :: "r"(dst), "l"(src), "r"(sz) : "memory")
#define CPCOMMIT() asm volatile("cp.async.commit_group;" ::: "memory")

#define LDSM_X4(r0, r1, r2, r3, addr) \
    asm volatile("ldmatrix.sync.aligned.m8n8.x4.shared.b16 {%0,%1,%2,%3}, [%4];" \
        : "=r"(r0), "=r"(r1), "=r"(r2), "=r"(r3) : "r"(addr))

#define MMA16816(d, a, b0, b1) \
    asm volatile("mma.sync.aligned.m16n8k16.row.col.f32.f16.f16.f32 " \
        "{%0,%1,%2,%3},{%4,%5,%6,%7},{%8,%9},{%0,%1,%2,%3};" \
        : "+f"((d)[0]), "+f"((d)[1]), "+f"((d)[2]), "+f"((d)[3]) \
        : "r"((a)[0]), "r"((a)[1]), "r"((a)[2]), "r"((a)[3]), "r"(b0), "r"(b1))

__device__ __forceinline__ float silu(float v) { return v / (1.f + __expf(-v)); }

// ---------------- 0) zero counters ----------------
__global__ void zero_kernel() {
    if (threadIdx.x < NEXP) g_counts[threadIdx.x] = 0;
}

// ---------------- 1) fused prep: gate (first), zero(out), cvt(w1) ----------------
#define NB_G  (NTOK / 8)                       // 256 gate blocks (dispatch first)
#define NB_Z  (NTOK * DIMV / 4 / 256)          // 2048
#define NB_W  (NEXP * HDIM * DIMV / 4 / 256)   // 16384 cvt(w1) blocks

__global__ void __launch_bounds__(256) prep_kernel(const float4* __restrict__ w1,
                                                   const float*  __restrict__ x,
                                                   const float*  __restrict__ gw,
                                                   const float*  __restrict__ bias,
                                                   float4* __restrict__ out4) {
    int b = blockIdx.x;
    int tid = threadIdx.x;

    if (b >= NB_G + NB_Z) {
        // ---- cvt(w1)
        int i = (b - NB_G - NB_Z) * 256 + tid;
        __half2* dst = (__half2*)g_w1h;
        float4 v = w1[i];
        dst[2 * i]     = __floats2half2_rn(v.x, v.y);
        dst[2 * i + 1] = __floats2half2_rn(v.z, v.w);
        return;
    }
    if (b >= NB_G) {
        int i = (b - NB_G) * 256 + tid;
        out4[i] = make_float4(0.f, 0.f, 0.f, 0.f);
        return;
    }

    // ---- gate role: warp per token (dispatched first, overlaps cvt waves)
    int wid = tid >> 5, lane = tid & 31;
    int t = b * 8 + wid;

    const float4* xr = (const float4*)(x + (size_t)t * DIMV);
    float4 xv[8];
#pragma unroll
    for (int i = 0; i < 8; i++) xv[i] = xr[lane + 32 * i];

    __half* xh = g_xh + (size_t)t * DIMV;
#pragma unroll
    for (int i = 0; i < 8; i++) {
        *(__half2*)(xh + (lane + 32 * i) * 4)     = __floats2half2_rn(xv[i].x, xv[i].y);
        *(__half2*)(xh + (lane + 32 * i) * 4 + 2) = __floats2half2_rn(xv[i].z, xv[i].w);
    }

    const float4* g4 = (const float4*)gw;
    float logit[NEXP];
#pragma unroll
    for (int e = 0; e < NEXP; e++) {
        float acc = 0.f;
#pragma unroll
        for (int i = 0; i < 8; i++) {
            float4 g = __ldg(&g4[e * 256 + lane + 32 * i]);
            acc += xv[i].x * g.x + xv[i].y * g.y + xv[i].z * g.z + xv[i].w * g.w;
        }
#pragma unroll
        for (int s = 16; s > 0; s >>= 1) acc += __shfl_xor_sync(0xFFFFFFFFu, acc, s);
        logit[e] = acc;
    }

    if (lane == 0) {
        float sc[NEXP];
#pragma unroll
        for (int e = 0; e < NEXP; e++)
            sc[e] = 1.f / (1.f + __expf(-(logit[e] + bias[e])));
        int i0 = 0;
#pragma unroll
        for (int e = 1; e < NEXP; e++) if (sc[e] > sc[i0]) i0 = e;
        int i1 = (i0 == 0) ? 1 : 0;
#pragma unroll
        for (int e = 0; e < NEXP; e++)
            if (e != i0 && sc[e] > sc[i1]) i1 = e;

        float s0 = sc[i0], s1 = sc[i1];
        float inv = 1.f / (s0 + s1 + 1e-6f);

        int slot0 = atomicAdd(&g_counts[i0], 1);
        g_perm[i0 * NTOK + slot0] = t;
        g_pw[i0 * NTOK + slot0]   = s0 * inv;
        int slot1 = atomicAdd(&g_counts[i1], 1);
        g_perm[i1 * NTOK + slot1] = t;
        g_pw[i1 * NTOK + slot1]   = s1 * inv;
    }
}

// ---------------- 2) offsets ----------------
__global__ void offsets_kernel() {
    if (threadIdx.x == 0) {
        int s = 0;
        for (int e = 0; e < NEXP; e++) { g_offsets[e] = s; s += g_counts[e]; }
    }
}

// ---------------- 3) fp16 mma.sync grouped GEMM, 512 threads ----------------
// C[128,256] = A[128,K] @ B[256,K]^T per expert tile.
// 16 warps as 4(m) x 4(n); warp tile 32x64; 3-stage cp.async, one sync/chunk.
// gemm1 (IS_G1): flattened 1-D grid of 3072 blocks; bid%3!=0 blocks convert w2
// fp32->fp16 (interleaved so they fill idle DRAM during the gemm waves).
template <int KTOT, int NTOTAL, bool IS_G1>
__global__ void __launch_bounds__(512, 1) gemm_mma(const __half* __restrict__ Ah,
                                                   const __half* __restrict__ Wh,
                                                   float* __restrict__ out,
                                                   const float4* __restrict__ w2src) {
    int e, m_idx, n_idx;
    int tid = threadIdx.x;
    if (IS_G1) {
        int bid = blockIdx.x;
        int r3 = bid % 3;
        if (r3) {
            // ---- interleaved cvt(w2) role: 2048 blocks x 512 thr x 4 float4
            int c = (bid / 3) * 2 + r3 - 1;
            __half2* dst = (__half2*)g_w2h;
#pragma unroll
            for (int j = 0; j < 4; j++) {
                int i = c * 2048 + j * 512 + tid;
                float4 v = w2src[i];
                dst[2 * i]     = __floats2half2_rn(v.x, v.y);
                dst[2 * i + 1] = __floats2half2_rn(v.z, v.w);
            }
            return;
        }
        int gidx = bid / 3;                 // 1024 gemm tiles
        n_idx = gidx & 7;
        m_idx = (gidx >> 3) & 15;
        e     = gidx >> 7;
    } else {
        n_idx = blockIdx.x;
        m_idx = blockIdx.y;
        e     = blockIdx.z;
    }

    int cnt = g_counts[e];
    int m0 = m_idx * MT;
    if (m0 >= cnt) return;
    int n0 = n_idx * NT;
    int off = g_offsets[e];

    extern __shared__ char smem[];
    uint32_t sb = smem_u32(smem);
    int wid = tid >> 5, lane = tid & 31;

    // ---- staging: A row = tid>>2 (4 thr/row, 2 x 16B each); B row = tid>>1 (2 thr/row, 4 x 16B)
    int ra = tid >> 2, qa = tid & 3;
    int rb = tid >> 1, qb = tid & 1;
    bool avalid = (m0 + ra) < cnt;
    const __half* asrc;
    if (IS_G1) {
        int tok = avalid ? g_perm[e * NTOK + m0 + ra] : 0;
        asrc = Ah + (size_t)tok * KTOT + qa * 16;
    } else {
        asrc = Ah + (size_t)(avalid ? (off + m0 + ra) : 0) * KTOT + qa * 16;
    }
    const __half* bsrc = Wh + (size_t)e * NTOTAL * KTOT + (size_t)(n0 + rb) * KTOT + qb * 32;
    uint32_t adst0 = sb + (uint32_t)ra * 128;
    uint32_t bdst0 = sb + SB_BASE + (uint32_t)rb * 128;
    uint32_t asz = avalid ? 16u : 0u;
    uint32_t rxa = (uint32_t)(ra & 7);
    uint32_t rxb = (uint32_t)(rb & 7);

    auto issue = [&](int kc, int st) {
        uint32_t ab = adst0 + st * SA_ST;
        const __half* as = asrc + kc * BK;
#pragma unroll
        for (int j = 0; j < 2; j++) {
            uint32_t ch = (uint32_t)(qa * 2 + j);
            CPASYNC16(ab + ((ch ^ rxa) << 4), as + j * 8, asz);
        }
        uint32_t bb = bdst0 + st * SB_ST;
        const __half* bs = bsrc + kc * BK;
#pragma unroll
        for (int j = 0; j < 4; j++) {
            uint32_t ch = (uint32_t)(qb * 4 + j);
            CPASYNC16(bb + ((ch ^ rxb) << 4), bs + j * 8, 16u);
        }
        CPCOMMIT();
    };

    // ---- fragment geometry: warp tile 32(m) x 64(n), warps 4m x 4n
    int wm = wid >> 2, wn = wid & 3;
    int m_base = wm * 32, n_base = wn * 64;
    int lr8 = lane & 7, q = lane >> 3;

    int rowA[2], rowB[4];
#pragma unroll
    for (int mi = 0; mi < 2; mi++) rowA[mi] = m_base + mi * 16 + (q & 1) * 8 + lr8;
#pragma unroll
    for (int np = 0; np < 4; np++) rowB[np] = n_base + np * 16 + (q >> 1) * 8 + lr8;

    float acc[2][8][4];
#pragma unroll
    for (int mi = 0; mi < 2; mi++)
#pragma unroll
        for (int nj = 0; nj < 8; nj++)
#pragma unroll
            for (int c = 0; c < 4; c++) acc[mi][nj][c] = 0.f;

    constexpr int NC = KTOT / BK;
    issue(0, 0);
    issue(1, 1);

    for (int kc = 0; kc < NC; kc++) {
        int st = kc % 3;
        if (kc + 1 < NC) {
            asm volatile("cp.async.wait_group 1;" ::: "memory");
        } else {
            asm volatile("cp.async.wait_group 0;" ::: "memory");
        }
        __syncthreads();
        if (kc + 2 < NC) issue(kc + 2, (kc + 2) % 3);

        uint32_t Ab = sb + st * SA_ST;
        uint32_t Bb = sb + SB_BASE + st * SB_ST;
#pragma unroll
        for (int s = 0; s < 4; s++) {
            uint32_t a[2][4];
#pragma unroll
            for (int mi = 0; mi < 2; mi++) {
                uint32_t ch = (uint32_t)(s * 2 + (q >> 1));
                uint32_t ad = Ab + (uint32_t)rowA[mi] * 128 + ((ch ^ (uint32_t)(rowA[mi] & 7)) << 4);
                LDSM_X4(a[mi][0], a[mi][1], a[mi][2], a[mi][3], ad);
            }
#pragma unroll
            for (int np = 0; np < 4; np++) {
                uint32_t b0, b1, b2, b3;
                uint32_t ch = (uint32_t)(s * 2 + (q & 1));
                uint32_t bd = Bb + (uint32_t)rowB[np] * 128 + ((ch ^ (uint32_t)(rowB[np] & 7)) << 4);
                LDSM_X4(b0, b1, b2, b3, bd);
#pragma unroll
                for (int mi = 0; mi < 2; mi++) {
                    MMA16816(acc[mi][2 * np],     a[mi], b0, b1);
                    MMA16816(acc[mi][2 * np + 1], a[mi], b2, b3);
                }
            }
        }
    }

    // ---- epilogue
    int g = lane >> 2, t2 = (lane & 3) * 2;
#pragma unroll
    for (int mi = 0; mi < 2; mi++) {
        int r0 = m_base + mi * 16 + g;
        int r1 = r0 + 8;
        bool v0 = (m0 + r0) < cnt;
        bool v1 = (m0 + r1) < cnt;
        if (IS_G1) {
            size_t gr0 = (size_t)(off + m0 + r0);
            size_t gr1 = (size_t)(off + m0 + r1);
#pragma unroll
            for (int nj = 0; nj < 8; nj++) {
                int col = n0 + n_base + nj * 8 + t2;
                if (v0)
                    *(__half2*)(g_hh + gr0 * NTOTAL + col) =
                        __floats2half2_rn(silu(acc[mi][nj][0]), silu(acc[mi][nj][1]));
                if (v1)
                    *(__half2*)(g_hh + gr1 * NTOTAL + col) =
                        __floats2half2_rn(silu(acc[mi][nj][2]), silu(acc[mi][nj][3]));
            }
        } else {
            int tok0 = 0, tok1 = 0;
            float wt0 = 0.f, wt1 = 0.f;
            if (v0) { tok0 = g_perm[e * NTOK + m0 + r0]; wt0 = g_pw[e * NTOK + m0 + r0]; }
            if (v1) { tok1 = g_perm[e * NTOK + m0 + r1]; wt1 = g_pw[e * NTOK + m0 + r1]; }
#pragma unroll
            for (int nj = 0; nj < 8; nj++) {
                int col = n0 + n_base + nj * 8 + t2;
                if (v0) {
                    float* o = out + (size_t)tok0 * DIMV + col;
                    atomicAdd(o,     wt0 * acc[mi][nj][0]);
                    atomicAdd(o + 1, wt0 * acc[mi][nj][1]);
                }
                if (v1) {
                    float* o = out + (size_t)tok1 * DIMV + col;
                    atomicAdd(o,     wt1 * acc[mi][nj][2]);
                    atomicAdd(o + 1, wt1 * acc[mi][nj][3]);
                }
            }
        }
    }
}

// ---------------- launch ----------------
extern "C" void kernel_launch(void* const* d_in, const int* in_sizes, int n_in,
                              void* d_out, int out_size) {
    const float* x      = (const float*)d_in[0];
    const float* gate_w = (const float*)d_in[1];
    const float* bias   = (const float*)d_in[2];
    const float* w1     = (const float*)d_in[3];
    const float* w2     = (const float*)d_in[4];
    float* out          = (float*)d_out;

    cudaFuncSetAttribute(gemm_mma<DIMV, HDIM, true>,
                         cudaFuncAttributeMaxDynamicSharedMemorySize, SMEM_BYTES);
    cudaFuncSetAttribute(gemm_mma<HDIM, DIMV, false>,
                         cudaFuncAttributeMaxDynamicSharedMemorySize, SMEM_BYTES);

    zero_kernel<<<1, 32>>>();
    prep_kernel<<<NB_G + NB_Z + NB_W, 256>>>((const float4*)w1, x, gate_w, bias, (float4*)out);
    offsets_kernel<<<1, 32>>>();

    __half* xh;  cudaGetSymbolAddress((void**)&xh, g_xh);
    __half* hh;  cudaGetSymbolAddress((void**)&hh, g_hh);
    __half* w1h; cudaGetSymbolAddress((void**)&w1h, g_w1h);
    __half* w2h; cudaGetSymbolAddress((void**)&w2h, g_w2h);

    // gemm1: 1024 gemm tiles + 2048 interleaved cvt(w2) blocks = 3072
    gemm_mma<DIMV, HDIM, true><<<3072, 512, SMEM_BYTES>>>(xh, w1h, nullptr, (const float4*)w2);
    // gemm2: R5 config (no K-split)
    gemm_mma<HDIM, DIMV, false><<<dim3(DIMV / NT, NTOK / MT, NEXP), 512, SMEM_BYTES>>>(hh, w2h, out, nullptr);
}